// round 2
// baseline (speedup 1.0000x reference)
#include <cuda_runtime.h>
#include <cuda_bf16.h>
#include <cstdint>

// Problem dims (fixed by the dataset)
#define S_LEN 128
#define B_SZ  16
#define H_DIM 1024
#define E_DIM 1024
#define G4    4096          // 4*H
#define V_SZ  50257

// ---------------- scratch (device globals; no allocation allowed) ----------
__device__ float g_xW [S_LEN * B_SZ * G4];     // x@W_ih^T + b_ih + b_hh  (S,B,4H)
__device__ float g_hs [S_LEN * B_SZ * H_DIM];  // LSTM hidden states      (S,B,H)
__device__ float g_outbuf[S_LEN * B_SZ * H_DIM]; // masked outputs        (S,B,H)
__device__ float g_c  [B_SZ * H_DIM];          // cell state
__device__ float g_hm [B_SZ * H_DIM];          // h0@Whm^T + bhm

// ---------------- f32x2 helpers (sm_103a packed fp32 FMA) ------------------
__device__ __forceinline__ unsigned long long dup2(float x) {
    unsigned long long r;
    asm("mov.b64 %0, {%1, %1};" : "=l"(r) : "f"(x));
    return r;
}
__device__ __forceinline__ unsigned long long pk2(float lo, float hi) {
    unsigned long long r;
    asm("mov.b64 %0, {%1, %2};" : "=l"(r) : "f"(lo), "f"(hi));
    return r;
}
__device__ __forceinline__ void fma2(unsigned long long& d,
                                     unsigned long long a, unsigned long long b) {
    asm("fma.rn.f32x2 %0, %1, %2, %0;" : "+l"(d) : "l"(a), "l"(b));
}
__device__ __forceinline__ float2 up2(unsigned long long v) {
    float2 f;
    asm("mov.b64 {%0, %1}, %2;" : "=f"(f.x), "=f"(f.y) : "l"(v));
    return f;
}
__device__ __forceinline__ float sigm(float x) { return 1.0f / (1.0f + expf(-x)); }

// ---------------- generic tiled fp32 GEMM:  C = A(MxK) * B(NxK)^T ----------
// MODE 0: C = acc + bias0[n]
// MODE 1: A rows gathered via gidx (embedding);  C = acc + bias0[n] + bias1[n]
// MODE 2: trans/mask: C = (row_s < *kptr) ? A[m][n] : acc + bias0[n] + hm[b][n]
template <int MODE>
__global__ void __launch_bounds__(256)
gemm_k(const float* __restrict__ A, const float* __restrict__ Bm,
       float* __restrict__ C, int M, int N, int K,
       const float* __restrict__ bias0, const float* __restrict__ bias1,
       const int* __restrict__ gidx, const float* __restrict__ hmv,
       const int* __restrict__ kptr)
{
    constexpr int BM = 128, BN = 128, BK = 16;
    __shared__ float As[BK][BM + 4];
    __shared__ float Bs[BK][BN + 4];

    const int tid = threadIdx.x;
    const int bm = blockIdx.y * BM;
    const int bn = blockIdx.x * BN;
    const int tx = tid & 15;        // n micro
    const int ty = tid >> 4;        // m micro

    // loader mapping: 2 float4 per thread per operand
    const int lr = tid >> 2;             // 0..63
    const int lk = (tid & 3) * 4;        // 0,4,8,12

    unsigned long long acc[8][4];
#pragma unroll
    for (int i = 0; i < 8; i++)
#pragma unroll
        for (int j = 0; j < 4; j++) acc[i][j] = 0ull;

    const float* arow0;
    const float* arow1;
    {
        int m0 = bm + lr, m1 = bm + lr + 64;
        if (MODE == 1) {
            arow0 = (m0 < M) ? A + (size_t)gidx[m0] * K : nullptr;
            arow1 = (m1 < M) ? A + (size_t)gidx[m1] * K : nullptr;
        } else {
            arow0 = (m0 < M) ? A + (size_t)m0 * K : nullptr;
            arow1 = (m1 < M) ? A + (size_t)m1 * K : nullptr;
        }
    }
    const int n0 = bn + lr, n1 = bn + lr + 64;
    const float* brow0 = (n0 < N) ? Bm + (size_t)n0 * K : nullptr;
    const float* brow1 = (n1 < N) ? Bm + (size_t)n1 * K : nullptr;

    const float4 fz = make_float4(0.f, 0.f, 0.f, 0.f);

    for (int k0 = 0; k0 < K; k0 += BK) {
        float4 a0 = arow0 ? *(const float4*)(arow0 + k0 + lk) : fz;
        float4 a1 = arow1 ? *(const float4*)(arow1 + k0 + lk) : fz;
        float4 b0 = brow0 ? *(const float4*)(brow0 + k0 + lk) : fz;
        float4 b1 = brow1 ? *(const float4*)(brow1 + k0 + lk) : fz;

        __syncthreads();   // previous tile consumers done
        As[lk + 0][lr] = a0.x;  As[lk + 1][lr] = a0.y;
        As[lk + 2][lr] = a0.z;  As[lk + 3][lr] = a0.w;
        As[lk + 0][lr + 64] = a1.x;  As[lk + 1][lr + 64] = a1.y;
        As[lk + 2][lr + 64] = a1.z;  As[lk + 3][lr + 64] = a1.w;
        Bs[lk + 0][lr] = b0.x;  Bs[lk + 1][lr] = b0.y;
        Bs[lk + 2][lr] = b0.z;  Bs[lk + 3][lr] = b0.w;
        Bs[lk + 0][lr + 64] = b1.x;  Bs[lk + 1][lr + 64] = b1.y;
        Bs[lk + 2][lr + 64] = b1.z;  Bs[lk + 3][lr + 64] = b1.w;
        __syncthreads();

#pragma unroll
        for (int kk = 0; kk < BK; kk++) {
            float4 av0 = *(const float4*)&As[kk][ty * 8];
            float4 av1 = *(const float4*)&As[kk][ty * 8 + 4];
            float4 bv0 = *(const float4*)&Bs[kk][tx * 8];
            float4 bv1 = *(const float4*)&Bs[kk][tx * 8 + 4];
            unsigned long long a2[8] = {dup2(av0.x), dup2(av0.y), dup2(av0.z), dup2(av0.w),
                                        dup2(av1.x), dup2(av1.y), dup2(av1.z), dup2(av1.w)};
            unsigned long long b2[4] = {pk2(bv0.x, bv0.y), pk2(bv0.z, bv0.w),
                                        pk2(bv1.x, bv1.y), pk2(bv1.z, bv1.w)};
#pragma unroll
            for (int i = 0; i < 8; i++)
#pragma unroll
                for (int j = 0; j < 4; j++) fma2(acc[i][j], a2[i], b2[j]);
        }
    }

    const int kval = (MODE == 2) ? *kptr : 0;

#pragma unroll
    for (int i = 0; i < 8; i++) {
        int m = bm + ty * 8 + i;
        if (m >= M) continue;
        size_t crow = (size_t)m * N;
        int srow = m >> 4;      // m / B
        int b    = m & 15;      // m % B
        bool cp = (MODE == 2) && (srow < kval);
#pragma unroll
        for (int j = 0; j < 4; j++) {
            float2 v = up2(acc[i][j]);
            int n = bn + tx * 8 + 2 * j;
            float vals[2] = {v.x, v.y};
#pragma unroll
            for (int u = 0; u < 2; u++) {
                int nn = n + u;
                if (nn >= N) continue;
                float r;
                if (MODE == 0)      r = vals[u] + bias0[nn];
                else if (MODE == 1) r = vals[u] + bias0[nn] + bias1[nn];
                else                r = cp ? A[(size_t)m * K + nn]
                                           : vals[u] + bias0[nn] + hmv[b * H_DIM + nn];
                C[crow + nn] = r;
            }
        }
    }
}

// ---------------- LSTM recurrent step --------------------------------------
// gates[b][j] = xW_t[b][j] + sum_e hprev[b][e] * Whh[j][e]
// 128 blocks; block bid owns hidden cols [bid*8, bid*8+8) -> 32 gate cols
// (i,f,g,o interleaved), all 16 batches. h staged transposed in smem.
#define HT_STRIDE 18
#define LSTM_SMEM ((H_DIM * HT_STRIDE + 32 * 16) * 4)

__global__ void lstm_step(const float* __restrict__ hprev,
                          const float* __restrict__ Whh,
                          const float* __restrict__ xWt,
                          float* __restrict__ c,
                          float* __restrict__ hout)
{
    extern __shared__ float sh[];
    float* hT = sh;                       // [e][b], stride HT_STRIDE
    float* sg = sh + H_DIM * HT_STRIDE;   // [32 colslots][16 b]

    const int tid = threadIdx.x;
    const int hb = blockIdx.x * 8;

    // stage h transposed
    const float4* hp4 = (const float4*)hprev;
#pragma unroll
    for (int it = 0; it < 16; it++) {
        int idx4 = tid + it * 256;
        float4 v = hp4[idx4];
        int gf = idx4 * 4;
        int b = gf >> 10;
        int e = gf & 1023;
        hT[(e + 0) * HT_STRIDE + b] = v.x;
        hT[(e + 1) * HT_STRIDE + b] = v.y;
        hT[(e + 2) * HT_STRIDE + b] = v.z;
        hT[(e + 3) * HT_STRIDE + b] = v.w;
    }
    __syncthreads();

    const int lc = tid >> 3;          // 0..31 col slot
    const int bo = tid & 7;
    const int b0 = bo * 2;
    const int g  = lc >> 3;           // gate 0..3
    const int hi = hb + (lc & 7);     // hidden index
    const int j  = g * 1024 + hi;     // gate column

    const float4* Wrow = (const float4*)(Whh + (size_t)j * H_DIM);
    unsigned long long accA = pk2(xWt[b0 * G4 + j], xWt[(b0 + 1) * G4 + j]);
    unsigned long long accB = 0ull;

#pragma unroll 4
    for (int e4 = 0; e4 < H_DIM / 4; e4++) {
        float4 w = __ldg(Wrow + e4);
        const float* hp = hT + (e4 * 4) * HT_STRIDE + b0;
        fma2(accA, dup2(w.x), *(const unsigned long long*)(hp));
        fma2(accB, dup2(w.y), *(const unsigned long long*)(hp + HT_STRIDE));
        fma2(accA, dup2(w.z), *(const unsigned long long*)(hp + 2 * HT_STRIDE));
        fma2(accB, dup2(w.w), *(const unsigned long long*)(hp + 3 * HT_STRIDE));
    }
    float2 va = up2(accA), vb = up2(accB);
    sg[lc * 16 + b0]     = va.x + vb.x;
    sg[lc * 16 + b0 + 1] = va.y + vb.y;
    __syncthreads();

    if (tid < 128) {
        int hil = tid >> 4;       // 0..7
        int b   = tid & 15;
        float gi = sg[(0  + hil) * 16 + b];
        float gf = sg[(8  + hil) * 16 + b];
        float gg = sg[(16 + hil) * 16 + b];
        float go = sg[(24 + hil) * 16 + b];
        int idx = b * H_DIM + hb + hil;
        float cn = sigm(gf) * c[idx] + sigm(gi) * tanhf(gg);
        c[idx] = cn;
        hout[idx] = sigm(go) * tanhf(cn);
    }
}

// ---------------- launcher --------------------------------------------------
extern "C" void kernel_launch(void* const* d_in, const int* in_sizes, int n_in,
                              void* d_out, int out_size)
{
    const int*   tokens = (const int*)  d_in[0];
    const float* h0     = (const float*)d_in[1];
    const float* c0     = (const float*)d_in[2];
    const float* emb    = (const float*)d_in[3];
    const float* Wih    = (const float*)d_in[4];
    const float* Whh    = (const float*)d_in[5];
    const float* bih    = (const float*)d_in[6];
    const float* bhh    = (const float*)d_in[7];
    const float* Whh2   = (const float*)d_in[8];
    const float* bhh2   = (const float*)d_in[9];
    const float* Whm    = (const float*)d_in[10];
    const float* bhm    = (const float*)d_in[11];
    const float* decW   = (const float*)d_in[12];
    const float* decb   = (const float*)d_in[13];
    const int*   kp     = (const int*)  d_in[14];
    float* out = (float*)d_out;

    void *p_xW, *p_hs, *p_outb, *p_c, *p_hm;
    cudaGetSymbolAddress(&p_xW,   g_xW);
    cudaGetSymbolAddress(&p_hs,   g_hs);
    cudaGetSymbolAddress(&p_outb, g_outbuf);
    cudaGetSymbolAddress(&p_c,    g_c);
    cudaGetSymbolAddress(&p_hm,   g_hm);
    float* xW  = (float*)p_xW;
    float* hs  = (float*)p_hs;
    float* ob  = (float*)p_outb;
    float* cbuf= (float*)p_c;
    float* hm  = (float*)p_hm;

    cudaFuncSetAttribute(lstm_step, cudaFuncAttributeMaxDynamicSharedMemorySize,
                         LSTM_SMEM);

    const int M = S_LEN * B_SZ;   // 2048

    // 1) xW = gather(emb, tokens) @ Wih^T + bih + bhh      (2048 x 4096)
    gemm_k<1><<<dim3(G4 / 128, M / 128), 256>>>(
        emb, Wih, xW, M, G4, E_DIM, bih, bhh, tokens, nullptr, nullptr);

    // 2) hm = h0 @ Whm^T + bhm                             (16 x 1024)
    gemm_k<0><<<dim3(H_DIM / 128, 1), 256>>>(
        h0, Whm, hm, B_SZ, H_DIM, H_DIM, bhm, nullptr, nullptr, nullptr, nullptr);

    // 3) c <- c0
    cudaMemcpyAsync(cbuf, c0, B_SZ * H_DIM * sizeof(float),
                    cudaMemcpyDeviceToDevice, 0);

    // 4) 128 recurrent steps
    for (int t = 0; t < S_LEN; t++) {
        const float* hp = (t == 0) ? h0 : (hs + (size_t)(t - 1) * B_SZ * H_DIM);
        lstm_step<<<128, 256, LSTM_SMEM>>>(
            hp, Whh, xW + (size_t)t * B_SZ * G4, cbuf,
            hs + (size_t)t * B_SZ * H_DIM);
    }

    // 5) outputs = (s<k) ? hs : hs @ Whh2^T + bhh2 + hm    (2048 x 1024)
    gemm_k<2><<<dim3(H_DIM / 128, M / 128), 256>>>(
        hs, Whh2, ob, M, H_DIM, H_DIM, bhh2, nullptr, nullptr, hm, kp);

    // 6) decoded = outputs @ decW^T + decb                 (2048 x 50257)
    gemm_k<0><<<dim3((V_SZ + 127) / 128, M / 128), 256>>>(
        ob, decW, out, M, V_SZ, H_DIM, decb, nullptr, nullptr, nullptr, nullptr);

    (void)in_sizes; (void)n_in; (void)out_size;
}

// round 3
// speedup vs baseline: 1.2934x; 1.2934x over previous
#include <cuda_runtime.h>
#include <cuda_bf16.h>
#include <cstdint>

// Problem dims (fixed by the dataset)
#define S_LEN 128
#define B_SZ  16
#define H_DIM 1024
#define E_DIM 1024
#define G4    4096          // 4*H
#define V_SZ  50257

// ---------------- scratch (device globals; no allocation allowed) ----------
__device__ float g_xW [S_LEN * B_SZ * G4];     // x@W_ih^T + b_ih + b_hh  (S,B,4H)
__device__ float g_hs [S_LEN * B_SZ * H_DIM];  // LSTM hidden states      (S,B,H)
__device__ float g_outbuf[S_LEN * B_SZ * H_DIM]; // masked outputs        (S,B,H)
__device__ float g_c  [B_SZ * H_DIM];          // cell state
__device__ float g_hm [B_SZ * H_DIM];          // h0@Whm^T + bhm

// ---------------- f32x2 helpers (sm_103a packed fp32 FMA) ------------------
__device__ __forceinline__ unsigned long long dup2(float x) {
    unsigned long long r;
    asm("mov.b64 %0, {%1, %1};" : "=l"(r) : "f"(x));
    return r;
}
__device__ __forceinline__ unsigned long long pk2(float lo, float hi) {
    unsigned long long r;
    asm("mov.b64 %0, {%1, %2};" : "=l"(r) : "f"(lo), "f"(hi));
    return r;
}
__device__ __forceinline__ void fma2(unsigned long long& d,
                                     unsigned long long a, unsigned long long b) {
    asm("fma.rn.f32x2 %0, %1, %2, %0;" : "+l"(d) : "l"(a), "l"(b));
}
__device__ __forceinline__ float2 up2(unsigned long long v) {
    float2 f;
    asm("mov.b64 {%0, %1}, %2;" : "=f"(f.x), "=f"(f.y) : "l"(v));
    return f;
}
__device__ __forceinline__ float sigm(float x) { return 1.0f / (1.0f + expf(-x)); }

// ---------------- generic tiled fp32 GEMM:  C = A(MxK) * B(NxK)^T ----------
// MODE 0: C = acc + bias0[n]
// MODE 1: A rows gathered via gidx (embedding);  C = acc + bias0[n] + bias1[n]
// MODE 2: trans/mask: C = (row_s < *kptr) ? A[m][n] : acc + bias0[n] + hm[b][n]
template <int MODE>
__global__ void __launch_bounds__(256)
gemm_k(const float* __restrict__ A, const float* __restrict__ Bm,
       float* __restrict__ C, int M, int N, int K,
       const float* __restrict__ bias0, const float* __restrict__ bias1,
       const int* __restrict__ gidx, const float* __restrict__ hmv,
       const int* __restrict__ kptr)
{
    constexpr int BM = 128, BN = 128, BK = 16;
    __shared__ float As[BK][BM + 4];
    __shared__ float Bs[BK][BN + 4];

    const int tid = threadIdx.x;
    const int bm = blockIdx.y * BM;
    const int bn = blockIdx.x * BN;
    const int tx = tid & 15;        // n micro
    const int ty = tid >> 4;        // m micro

    // loader mapping: 2 float4 per thread per operand
    const int lr = tid >> 2;             // 0..63
    const int lk = (tid & 3) * 4;        // 0,4,8,12

    unsigned long long acc[8][4];
#pragma unroll
    for (int i = 0; i < 8; i++)
#pragma unroll
        for (int j = 0; j < 4; j++) acc[i][j] = 0ull;

    const float* arow0;
    const float* arow1;
    {
        int m0 = bm + lr, m1 = bm + lr + 64;
        if (MODE == 1) {
            arow0 = (m0 < M) ? A + (size_t)gidx[m0] * K : nullptr;
            arow1 = (m1 < M) ? A + (size_t)gidx[m1] * K : nullptr;
        } else {
            arow0 = (m0 < M) ? A + (size_t)m0 * K : nullptr;
            arow1 = (m1 < M) ? A + (size_t)m1 * K : nullptr;
        }
    }
    const int n0 = bn + lr, n1 = bn + lr + 64;
    const float* brow0 = (n0 < N) ? Bm + (size_t)n0 * K : nullptr;
    const float* brow1 = (n1 < N) ? Bm + (size_t)n1 * K : nullptr;

    const float4 fz = make_float4(0.f, 0.f, 0.f, 0.f);

    for (int k0 = 0; k0 < K; k0 += BK) {
        float4 a0 = arow0 ? *(const float4*)(arow0 + k0 + lk) : fz;
        float4 a1 = arow1 ? *(const float4*)(arow1 + k0 + lk) : fz;
        float4 b0 = brow0 ? *(const float4*)(brow0 + k0 + lk) : fz;
        float4 b1 = brow1 ? *(const float4*)(brow1 + k0 + lk) : fz;

        __syncthreads();   // previous tile consumers done
        As[lk + 0][lr] = a0.x;  As[lk + 1][lr] = a0.y;
        As[lk + 2][lr] = a0.z;  As[lk + 3][lr] = a0.w;
        As[lk + 0][lr + 64] = a1.x;  As[lk + 1][lr + 64] = a1.y;
        As[lk + 2][lr + 64] = a1.z;  As[lk + 3][lr + 64] = a1.w;
        Bs[lk + 0][lr] = b0.x;  Bs[lk + 1][lr] = b0.y;
        Bs[lk + 2][lr] = b0.z;  Bs[lk + 3][lr] = b0.w;
        Bs[lk + 0][lr + 64] = b1.x;  Bs[lk + 1][lr + 64] = b1.y;
        Bs[lk + 2][lr + 64] = b1.z;  Bs[lk + 3][lr + 64] = b1.w;
        __syncthreads();

#pragma unroll
        for (int kk = 0; kk < BK; kk++) {
            float4 av0 = *(const float4*)&As[kk][ty * 8];
            float4 av1 = *(const float4*)&As[kk][ty * 8 + 4];
            float4 bv0 = *(const float4*)&Bs[kk][tx * 8];
            float4 bv1 = *(const float4*)&Bs[kk][tx * 8 + 4];
            unsigned long long a2[8] = {dup2(av0.x), dup2(av0.y), dup2(av0.z), dup2(av0.w),
                                        dup2(av1.x), dup2(av1.y), dup2(av1.z), dup2(av1.w)};
            unsigned long long b2[4] = {pk2(bv0.x, bv0.y), pk2(bv0.z, bv0.w),
                                        pk2(bv1.x, bv1.y), pk2(bv1.z, bv1.w)};
#pragma unroll
            for (int i = 0; i < 8; i++)
#pragma unroll
                for (int j = 0; j < 4; j++) fma2(acc[i][j], a2[i], b2[j]);
        }
    }

    const int kval = (MODE == 2) ? *kptr : 0;

#pragma unroll
    for (int i = 0; i < 8; i++) {
        int m = bm + ty * 8 + i;
        if (m >= M) continue;
        size_t crow = (size_t)m * N;
        int srow = m >> 4;      // m / B
        int b    = m & 15;      // m % B
        bool cp = (MODE == 2) && (srow < kval);
#pragma unroll
        for (int j = 0; j < 4; j++) {
            float2 v = up2(acc[i][j]);
            int n = bn + tx * 8 + 2 * j;
            float vals[2] = {v.x, v.y};
#pragma unroll
            for (int u = 0; u < 2; u++) {
                int nn = n + u;
                if (nn >= N) continue;
                float r;
                if (MODE == 0)      r = vals[u] + bias0[nn];
                else if (MODE == 1) r = vals[u] + bias0[nn] + bias1[nn];
                else                r = cp ? A[(size_t)m * K + nn]
                                           : vals[u] + bias0[nn] + hmv[b * H_DIM + nn];
                C[crow + nn] = r;
            }
        }
    }
}

// ---------------- LSTM recurrent step (rewritten) ---------------------------
// gates[b][j] = xW_t[b][j] + sum_e h[b][e] * Whh[j][e]
// grid 128: block owns 8 hidden cols (hb..hb+7) x 4 gates = 32 gate cols, all b.
// 256 threads: lane kt = tid&31 owns k in {kt, kt+32, ...} (interleaved);
// warp jt = tid>>5 owns 4 gate cols. Acc = 4 cols x 8 b-pairs in f32x2.
// h staged transposed in smem, row stride 18 floats (conflict-free LDS.64).
// Partials reduced via padded smem (stride 514), then fused activation.
#define HT_STRIDE 18
#define PF_STRIDE 514
#define HT_FLOATS (H_DIM * HT_STRIDE)            // 18432
#define PF_FLOATS (32 * PF_STRIDE)               // 16448
#define SG_FLOATS 512
#define LSTM_SMEM ((HT_FLOATS + PF_FLOATS + SG_FLOATS) * 4)   // 141568 B

__global__ void __launch_bounds__(256, 1)
lstm_step(const float* __restrict__ hprev,
          const float* __restrict__ Whh,
          const float* __restrict__ xWt,
          float* __restrict__ c,
          float* __restrict__ hout)
{
    extern __shared__ float sh[];
    float* hT = sh;                          // [1024][18]  (e-major, b fast)
    float* pf = sh + HT_FLOATS;              // [32 kt][514]
    float* sg = sh + HT_FLOATS + PF_FLOATS;  // [32 l][16 b]

    const int tid = threadIdx.x;
    const int hb  = blockIdx.x * 8;

    // ---- stage h transposed: lane-b-major loads -> ~2-way STS conflicts ----
    {
        const int b   = tid & 15;
        const int e4b = tid >> 4;            // 0..15
        const float4* hp = (const float4*)(hprev + b * H_DIM);
#pragma unroll
        for (int i = 0; i < 16; i++) {
            int e4 = e4b + 16 * i;
            float4 v = hp[e4];
            int e0 = e4 * 4;
            hT[(e0 + 0) * HT_STRIDE + b] = v.x;
            hT[(e0 + 1) * HT_STRIDE + b] = v.y;
            hT[(e0 + 2) * HT_STRIDE + b] = v.z;
            hT[(e0 + 3) * HT_STRIDE + b] = v.w;
        }
    }
    __syncthreads();

    // ---- main partial GEMM ----
    const int kt = tid & 31;
    const int jt = tid >> 5;                 // warp id; owns l = jt*4 .. +3

    const float* wp[4];
#pragma unroll
    for (int l = 0; l < 4; l++) {
        int ll = jt * 4 + l;                         // 0..31
        int j  = (ll >> 3) * H_DIM + hb + (ll & 7);  // gate*1024 + hidden
        wp[l] = Whh + (size_t)j * H_DIM + kt;
    }

    unsigned long long acc[4][8];
#pragma unroll
    for (int l = 0; l < 4; l++)
#pragma unroll
        for (int bp = 0; bp < 8; bp++) acc[l][bp] = 0ull;

    float wc[4];
#pragma unroll
    for (int l = 0; l < 4; l++) wc[l] = __ldg(wp[l]);

#pragma unroll 4
    for (int i = 0; i < 32; i++) {
        // prefetch next W (wraps to 0 on last iter; harmless in-bounds reload)
        float wn[4];
        int nxt = ((i + 1) & 31) * 32;
#pragma unroll
        for (int l = 0; l < 4; l++) wn[l] = __ldg(wp[l] + nxt);

        const int k = kt + 32 * i;
        const unsigned long long* hrow =
            (const unsigned long long*)(hT + k * HT_STRIDE);
        unsigned long long hv[8];
#pragma unroll
        for (int bp = 0; bp < 8; bp++) hv[bp] = hrow[bp];

#pragma unroll
        for (int l = 0; l < 4; l++) {
            unsigned long long wd = dup2(wc[l]);
#pragma unroll
            for (int bp = 0; bp < 8; bp++) fma2(acc[l][bp], wd, hv[bp]);
        }
#pragma unroll
        for (int l = 0; l < 4; l++) wc[l] = wn[l];
    }

    // ---- write partials (conflict-free: word = kt*514 + 2*tid') ----
    {
        unsigned long long* pr =
            (unsigned long long*)(pf + kt * PF_STRIDE + (jt * 4) * 16);
#pragma unroll
        for (int l = 0; l < 4; l++)
#pragma unroll
            for (int bp = 0; bp < 8; bp++) pr[l * 8 + bp] = acc[l][bp];
    }
    __syncthreads();

    // ---- reduce over kt, add xW, stash gates ----
    {
        const int l = tid >> 3;              // 0..31
        const int b = (tid & 7) * 2;         // 0,2,..,14
        float s0 = 0.f, s1 = 0.f;
        const float* p = pf + l * 16 + b;
#pragma unroll 8
        for (int ktt = 0; ktt < 32; ktt++) {
            float2 v = *(const float2*)(p + ktt * PF_STRIDE);
            s0 += v.x; s1 += v.y;
        }
        const int j = (l >> 3) * H_DIM + hb + (l & 7);
        sg[l * 16 + b]     = s0 + xWt[b * G4 + j];
        sg[l * 16 + b + 1] = s1 + xWt[(b + 1) * G4 + j];
    }
    __syncthreads();

    // ---- activation + state update ----
    if (tid < 128) {
        int hil = tid >> 4;       // 0..7
        int b   = tid & 15;
        float gi = sg[(0  + hil) * 16 + b];
        float gf = sg[(8  + hil) * 16 + b];
        float gg = sg[(16 + hil) * 16 + b];
        float go = sg[(24 + hil) * 16 + b];
        int idx = b * H_DIM + hb + hil;
        float cn = sigm(gf) * c[idx] + sigm(gi) * tanhf(gg);
        c[idx] = cn;
        hout[idx] = sigm(go) * tanhf(cn);
    }
}

// ---------------- launcher --------------------------------------------------
extern "C" void kernel_launch(void* const* d_in, const int* in_sizes, int n_in,
                              void* d_out, int out_size)
{
    const int*   tokens = (const int*)  d_in[0];
    const float* h0     = (const float*)d_in[1];
    const float* c0     = (const float*)d_in[2];
    const float* emb    = (const float*)d_in[3];
    const float* Wih    = (const float*)d_in[4];
    const float* Whh    = (const float*)d_in[5];
    const float* bih    = (const float*)d_in[6];
    const float* bhh    = (const float*)d_in[7];
    const float* Whh2   = (const float*)d_in[8];
    const float* bhh2   = (const float*)d_in[9];
    const float* Whm    = (const float*)d_in[10];
    const float* bhm    = (const float*)d_in[11];
    const float* decW   = (const float*)d_in[12];
    const float* decb   = (const float*)d_in[13];
    const int*   kp     = (const int*)  d_in[14];
    float* out = (float*)d_out;

    void *p_xW, *p_hs, *p_outb, *p_c, *p_hm;
    cudaGetSymbolAddress(&p_xW,   g_xW);
    cudaGetSymbolAddress(&p_hs,   g_hs);
    cudaGetSymbolAddress(&p_outb, g_outbuf);
    cudaGetSymbolAddress(&p_c,    g_c);
    cudaGetSymbolAddress(&p_hm,   g_hm);
    float* xW  = (float*)p_xW;
    float* hs  = (float*)p_hs;
    float* ob  = (float*)p_outb;
    float* cbuf= (float*)p_c;
    float* hm  = (float*)p_hm;

    cudaFuncSetAttribute(lstm_step, cudaFuncAttributeMaxDynamicSharedMemorySize,
                         LSTM_SMEM);

    const int M = S_LEN * B_SZ;   // 2048

    // 1) xW = gather(emb, tokens) @ Wih^T + bih + bhh      (2048 x 4096)
    gemm_k<1><<<dim3(G4 / 128, M / 128), 256>>>(
        emb, Wih, xW, M, G4, E_DIM, bih, bhh, tokens, nullptr, nullptr);

    // 2) hm = h0 @ Whm^T + bhm                             (16 x 1024)
    gemm_k<0><<<dim3(H_DIM / 128, 1), 256>>>(
        h0, Whm, hm, B_SZ, H_DIM, H_DIM, bhm, nullptr, nullptr, nullptr, nullptr);

    // 3) c <- c0
    cudaMemcpyAsync(cbuf, c0, B_SZ * H_DIM * sizeof(float),
                    cudaMemcpyDeviceToDevice, 0);

    // 4) 128 recurrent steps
    for (int t = 0; t < S_LEN; t++) {
        const float* hp = (t == 0) ? h0 : (hs + (size_t)(t - 1) * B_SZ * H_DIM);
        lstm_step<<<128, 256, LSTM_SMEM>>>(
            hp, Whh, xW + (size_t)t * B_SZ * G4, cbuf,
            hs + (size_t)t * B_SZ * H_DIM);
    }

    // 5) outputs = (s<k) ? hs : hs @ Whh2^T + bhh2 + hm    (2048 x 1024)
    gemm_k<2><<<dim3(H_DIM / 128, M / 128), 256>>>(
        hs, Whh2, ob, M, H_DIM, H_DIM, bhh2, nullptr, nullptr, hm, kp);

    // 6) decoded = outputs @ decW^T + decb                 (2048 x 50257)
    gemm_k<0><<<dim3((V_SZ + 127) / 128, M / 128), 256>>>(
        ob, decW, out, M, V_SZ, H_DIM, decb, nullptr, nullptr, nullptr, nullptr);

    (void)in_sizes; (void)n_in; (void)out_size;
}

// round 5
// speedup vs baseline: 1.5379x; 1.1891x over previous
#include <cuda_runtime.h>
#include <cuda_bf16.h>
#include <cstdint>

// Problem dims (fixed by the dataset)
#define S_LEN 128
#define B_SZ  16
#define H_DIM 1024
#define E_DIM 1024
#define G4    4096
#define V_SZ  50257
#define V_PAD 50304          // 393 * 128

// ---------------- scratch (device globals; no allocation allowed) ----------
__device__ float g_xW [S_LEN * B_SZ * G4];
__device__ float g_hs [S_LEN * B_SZ * H_DIM];
__device__ float g_outbuf[S_LEN * B_SZ * H_DIM];
__device__ float g_c  [B_SZ * H_DIM];
__device__ float g_hm [B_SZ * H_DIM];
__device__ __align__(256) __nv_bfloat16 g_a_hi[S_LEN * B_SZ * H_DIM];
__device__ __align__(256) __nv_bfloat16 g_a_lo[S_LEN * B_SZ * H_DIM];
__device__ __align__(256) __nv_bfloat16 g_b_hi[(size_t)V_PAD * H_DIM];
__device__ __align__(256) __nv_bfloat16 g_b_lo[(size_t)V_PAD * H_DIM];

// ---------------- f32x2 helpers --------------------------------------------
__device__ __forceinline__ unsigned long long dup2(float x) {
    unsigned long long r; asm("mov.b64 %0, {%1, %1};" : "=l"(r) : "f"(x)); return r;
}
__device__ __forceinline__ unsigned long long pk2(float lo, float hi) {
    unsigned long long r; asm("mov.b64 %0, {%1, %2};" : "=l"(r) : "f"(lo), "f"(hi)); return r;
}
__device__ __forceinline__ void fma2(unsigned long long& d,
                                     unsigned long long a, unsigned long long b) {
    asm("fma.rn.f32x2 %0, %1, %2, %0;" : "+l"(d) : "l"(a), "l"(b));
}
__device__ __forceinline__ float2 up2(unsigned long long v) {
    float2 f; asm("mov.b64 {%0, %1}, %2;" : "=f"(f.x), "=f"(f.y) : "l"(v)); return f;
}
__device__ __forceinline__ float sigm(float x) { return 1.0f / (1.0f + expf(-x)); }

__device__ __forceinline__ uint32_t smem_u32(const void* p) {
    uint32_t a;
    asm("{ .reg .u64 t; cvta.to.shared.u64 t, %1; cvt.u32.u64 %0, t; }"
        : "=r"(a) : "l"(p));
    return a;
}

// ---------------- mma.sync / ldmatrix / cp.async helpers (non-'a' PTX) ------
__device__ __forceinline__ void ldsm_x4(uint32_t* r, uint32_t addr) {
    asm volatile("ldmatrix.sync.aligned.m8n8.x4.shared.b16 {%0,%1,%2,%3}, [%4];"
                 : "=r"(r[0]), "=r"(r[1]), "=r"(r[2]), "=r"(r[3]) : "r"(addr));
}
__device__ __forceinline__ void mma16816(float* c, const uint32_t* a, const uint32_t* b) {
    asm volatile(
        "mma.sync.aligned.m16n8k16.row.col.f32.bf16.bf16.f32 "
        "{%0,%1,%2,%3}, {%4,%5,%6,%7}, {%8,%9}, {%0,%1,%2,%3};"
        : "+f"(c[0]), "+f"(c[1]), "+f"(c[2]), "+f"(c[3])
        : "r"(a[0]), "r"(a[1]), "r"(a[2]), "r"(a[3]), "r"(b[0]), "r"(b[1]));
}
__device__ __forceinline__ void cp16(uint32_t dst, const void* src) {
    asm volatile("cp.async.cg.shared.global [%0], [%1], 16;" :: "r"(dst), "l"(src));
}
#define CP_COMMIT() asm volatile("cp.async.commit_group;" ::: "memory")
#define CP_WAIT1()  asm volatile("cp.async.wait_group 1;" ::: "memory")
#define CP_WAIT0()  asm volatile("cp.async.wait_group 0;" ::: "memory")

// ---------------- generic tiled fp32 GEMM (steps 1,2,5) ---------------------
template <int MODE>
__global__ void __launch_bounds__(256)
gemm_k(const float* __restrict__ A, const float* __restrict__ Bm,
       float* __restrict__ C, int M, int N, int K,
       const float* __restrict__ bias0, const float* __restrict__ bias1,
       const int* __restrict__ gidx, const float* __restrict__ hmv,
       const int* __restrict__ kptr)
{
    constexpr int BM = 128, BN = 128, BK = 16;
    __shared__ float As[BK][BM + 4];
    __shared__ float Bs[BK][BN + 4];

    const int tid = threadIdx.x;
    const int bm = blockIdx.y * BM;
    const int bn = blockIdx.x * BN;
    const int tx = tid & 15;
    const int ty = tid >> 4;
    const int lr = tid >> 2;
    const int lk = (tid & 3) * 4;

    unsigned long long acc[8][4];
#pragma unroll
    for (int i = 0; i < 8; i++)
#pragma unroll
        for (int j = 0; j < 4; j++) acc[i][j] = 0ull;

    const float* arow0;
    const float* arow1;
    {
        int m0 = bm + lr, m1 = bm + lr + 64;
        if (MODE == 1) {
            arow0 = (m0 < M) ? A + (size_t)gidx[m0] * K : nullptr;
            arow1 = (m1 < M) ? A + (size_t)gidx[m1] * K : nullptr;
        } else {
            arow0 = (m0 < M) ? A + (size_t)m0 * K : nullptr;
            arow1 = (m1 < M) ? A + (size_t)m1 * K : nullptr;
        }
    }
    const int n0 = bn + lr, n1 = bn + lr + 64;
    const float* brow0 = (n0 < N) ? Bm + (size_t)n0 * K : nullptr;
    const float* brow1 = (n1 < N) ? Bm + (size_t)n1 * K : nullptr;

    const float4 fz = make_float4(0.f, 0.f, 0.f, 0.f);

    for (int k0 = 0; k0 < K; k0 += BK) {
        float4 a0 = arow0 ? *(const float4*)(arow0 + k0 + lk) : fz;
        float4 a1 = arow1 ? *(const float4*)(arow1 + k0 + lk) : fz;
        float4 b0 = brow0 ? *(const float4*)(brow0 + k0 + lk) : fz;
        float4 b1 = brow1 ? *(const float4*)(brow1 + k0 + lk) : fz;

        __syncthreads();
        As[lk + 0][lr] = a0.x;  As[lk + 1][lr] = a0.y;
        As[lk + 2][lr] = a0.z;  As[lk + 3][lr] = a0.w;
        As[lk + 0][lr + 64] = a1.x;  As[lk + 1][lr + 64] = a1.y;
        As[lk + 2][lr + 64] = a1.z;  As[lk + 3][lr + 64] = a1.w;
        Bs[lk + 0][lr] = b0.x;  Bs[lk + 1][lr] = b0.y;
        Bs[lk + 2][lr] = b0.z;  Bs[lk + 3][lr] = b0.w;
        Bs[lk + 0][lr + 64] = b1.x;  Bs[lk + 1][lr + 64] = b1.y;
        Bs[lk + 2][lr + 64] = b1.z;  Bs[lk + 3][lr + 64] = b1.w;
        __syncthreads();

#pragma unroll
        for (int kk = 0; kk < BK; kk++) {
            float4 av0 = *(const float4*)&As[kk][ty * 8];
            float4 av1 = *(const float4*)&As[kk][ty * 8 + 4];
            float4 bv0 = *(const float4*)&Bs[kk][tx * 8];
            float4 bv1 = *(const float4*)&Bs[kk][tx * 8 + 4];
            unsigned long long a2[8] = {dup2(av0.x), dup2(av0.y), dup2(av0.z), dup2(av0.w),
                                        dup2(av1.x), dup2(av1.y), dup2(av1.z), dup2(av1.w)};
            unsigned long long b2[4] = {pk2(bv0.x, bv0.y), pk2(bv0.z, bv0.w),
                                        pk2(bv1.x, bv1.y), pk2(bv1.z, bv1.w)};
#pragma unroll
            for (int i = 0; i < 8; i++)
#pragma unroll
                for (int j = 0; j < 4; j++) fma2(acc[i][j], a2[i], b2[j]);
        }
    }

    const int kval = (MODE == 2) ? *kptr : 0;

#pragma unroll
    for (int i = 0; i < 8; i++) {
        int m = bm + ty * 8 + i;
        if (m >= M) continue;
        size_t crow = (size_t)m * N;
        int srow = m >> 4;
        int b    = m & 15;
        bool cp = (MODE == 2) && (srow < kval);
#pragma unroll
        for (int j = 0; j < 4; j++) {
            float2 v = up2(acc[i][j]);
            int n = bn + tx * 8 + 2 * j;
            float vals[2] = {v.x, v.y};
#pragma unroll
            for (int u = 0; u < 2; u++) {
                int nn = n + u;
                if (nn >= N) continue;
                float r;
                if (MODE == 0)      r = vals[u] + bias0[nn];
                else if (MODE == 1) r = vals[u] + bias0[nn] + bias1[nn];
                else                r = cp ? A[(size_t)m * K + nn]
                                           : vals[u] + bias0[nn] + hmv[b * H_DIM + nn];
                C[crow + nn] = r;
            }
        }
    }
}

// ---------------- LSTM recurrent step (unchanged) ---------------------------
#define HT_STRIDE 18
#define PF_STRIDE 514
#define HT_FLOATS (H_DIM * HT_STRIDE)
#define PF_FLOATS (32 * PF_STRIDE)
#define SG_FLOATS 512
#define LSTM_SMEM ((HT_FLOATS + PF_FLOATS + SG_FLOATS) * 4)

__global__ void __launch_bounds__(256, 1)
lstm_step(const float* __restrict__ hprev,
          const float* __restrict__ Whh,
          const float* __restrict__ xWt,
          float* __restrict__ c,
          float* __restrict__ hout)
{
    extern __shared__ float sh[];
    float* hT = sh;
    float* pf = sh + HT_FLOATS;
    float* sg = sh + HT_FLOATS + PF_FLOATS;

    const int tid = threadIdx.x;
    const int hb  = blockIdx.x * 8;

    {
        const int b   = tid & 15;
        const int e4b = tid >> 4;
        const float4* hp = (const float4*)(hprev + b * H_DIM);
#pragma unroll
        for (int i = 0; i < 16; i++) {
            int e4 = e4b + 16 * i;
            float4 v = hp[e4];
            int e0 = e4 * 4;
            hT[(e0 + 0) * HT_STRIDE + b] = v.x;
            hT[(e0 + 1) * HT_STRIDE + b] = v.y;
            hT[(e0 + 2) * HT_STRIDE + b] = v.z;
            hT[(e0 + 3) * HT_STRIDE + b] = v.w;
        }
    }
    __syncthreads();

    const int kt = tid & 31;
    const int jt = tid >> 5;

    const float* wp[4];
#pragma unroll
    for (int l = 0; l < 4; l++) {
        int ll = jt * 4 + l;
        int j  = (ll >> 3) * H_DIM + hb + (ll & 7);
        wp[l] = Whh + (size_t)j * H_DIM + kt;
    }

    unsigned long long acc[4][8];
#pragma unroll
    for (int l = 0; l < 4; l++)
#pragma unroll
        for (int bp = 0; bp < 8; bp++) acc[l][bp] = 0ull;

    float wc[4];
#pragma unroll
    for (int l = 0; l < 4; l++) wc[l] = __ldg(wp[l]);

#pragma unroll 4
    for (int i = 0; i < 32; i++) {
        float wn[4];
        int nxt = ((i + 1) & 31) * 32;
#pragma unroll
        for (int l = 0; l < 4; l++) wn[l] = __ldg(wp[l] + nxt);

        const int k = kt + 32 * i;
        const unsigned long long* hrow =
            (const unsigned long long*)(hT + k * HT_STRIDE);
        unsigned long long hv[8];
#pragma unroll
        for (int bp = 0; bp < 8; bp++) hv[bp] = hrow[bp];

#pragma unroll
        for (int l = 0; l < 4; l++) {
            unsigned long long wd = dup2(wc[l]);
#pragma unroll
            for (int bp = 0; bp < 8; bp++) fma2(acc[l][bp], wd, hv[bp]);
        }
#pragma unroll
        for (int l = 0; l < 4; l++) wc[l] = wn[l];
    }

    {
        unsigned long long* pr =
            (unsigned long long*)(pf + kt * PF_STRIDE + (jt * 4) * 16);
#pragma unroll
        for (int l = 0; l < 4; l++)
#pragma unroll
            for (int bp = 0; bp < 8; bp++) pr[l * 8 + bp] = acc[l][bp];
    }
    __syncthreads();

    {
        const int l = tid >> 3;
        const int b = (tid & 7) * 2;
        float s0 = 0.f, s1 = 0.f;
        const float* p = pf + l * 16 + b;
#pragma unroll 8
        for (int ktt = 0; ktt < 32; ktt++) {
            float2 v = *(const float2*)(p + ktt * PF_STRIDE);
            s0 += v.x; s1 += v.y;
        }
        const int j = (l >> 3) * H_DIM + hb + (l & 7);
        sg[l * 16 + b]     = s0 + xWt[b * G4 + j];
        sg[l * 16 + b + 1] = s1 + xWt[(b + 1) * G4 + j];
    }
    __syncthreads();

    if (tid < 128) {
        int hil = tid >> 4;
        int b   = tid & 15;
        float gi = sg[(0  + hil) * 16 + b];
        float gf = sg[(8  + hil) * 16 + b];
        float gg = sg[(16 + hil) * 16 + b];
        float go = sg[(24 + hil) * 16 + b];
        int idx = b * H_DIM + hb + hil;
        float cn = sigm(gf) * c[idx] + sigm(gi) * tanhf(gg);
        c[idx] = cn;
        hout[idx] = sigm(go) * tanhf(cn);
    }
}

// ---------------- bf16 hi/lo split kernels ----------------------------------
__global__ void __launch_bounds__(256)
split_a_k(const float* __restrict__ src, __nv_bfloat16* __restrict__ hi,
          __nv_bfloat16* __restrict__ lo, int n4)
{
    int i = blockIdx.x * blockDim.x + threadIdx.x;
    if (i >= n4) return;
    float4 v = ((const float4*)src)[i];
    float xs[4] = {v.x, v.y, v.z, v.w};
    __nv_bfloat16 h[4], l[4];
#pragma unroll
    for (int j = 0; j < 4; j++) {
        h[j] = __float2bfloat16_rn(xs[j]);
        l[j] = __float2bfloat16_rn(xs[j] - __bfloat162float(h[j]));
    }
    ((__nv_bfloat162*)hi)[2 * i]     = __halves2bfloat162(h[0], h[1]);
    ((__nv_bfloat162*)hi)[2 * i + 1] = __halves2bfloat162(h[2], h[3]);
    ((__nv_bfloat162*)lo)[2 * i]     = __halves2bfloat162(l[0], l[1]);
    ((__nv_bfloat162*)lo)[2 * i + 1] = __halves2bfloat162(l[2], l[3]);
}

__global__ void __launch_bounds__(256)
split_b_k(const float* __restrict__ src, __nv_bfloat16* __restrict__ hi,
          __nv_bfloat16* __restrict__ lo)
{
    int i = blockIdx.x * blockDim.x + threadIdx.x;   // over V_PAD*1024/4
    if (i >= V_PAD * (H_DIM / 4)) return;
    int row = i >> 8;
    float4 v = make_float4(0.f, 0.f, 0.f, 0.f);
    if (row < V_SZ) v = ((const float4*)src)[i];
    float xs[4] = {v.x, v.y, v.z, v.w};
    __nv_bfloat16 h[4], l[4];
#pragma unroll
    for (int j = 0; j < 4; j++) {
        h[j] = __float2bfloat16_rn(xs[j]);
        l[j] = __float2bfloat16_rn(xs[j] - __bfloat162float(h[j]));
    }
    ((__nv_bfloat162*)hi)[2 * i]     = __halves2bfloat162(h[0], h[1]);
    ((__nv_bfloat162*)hi)[2 * i + 1] = __halves2bfloat162(h[2], h[3]);
    ((__nv_bfloat162*)lo)[2 * i]     = __halves2bfloat162(l[0], l[1]);
    ((__nv_bfloat162*)lo)[2 * i + 1] = __halves2bfloat162(l[2], l[3]);
}

// ---------------- mma.sync decoder GEMM -------------------------------------
// C[2048, V] = A[2048,1024] * B[V,1024]^T + bias, bf16 3-pass split:
//   D = Ahi*Bhi + Ahi*Blo + Alo*Bhi  (fp32 accumulators persist across passes)
// CTA 128x128, BK=32, 8 warps (2M x 4N, warp tile 64x32), cp.async 2-stage.
// smem rows padded to 80B (40 bf16): ldmatrix chunk group = (5*row+c) mod 8,
// distinct over 8 consecutive rows -> conflict-free.
#define DROW 40

__global__ void __launch_bounds__(256, 1)
dec_gemm(const __nv_bfloat16* __restrict__ a_hi, const __nv_bfloat16* __restrict__ a_lo,
         const __nv_bfloat16* __restrict__ b_hi, const __nv_bfloat16* __restrict__ b_lo,
         const float* __restrict__ bias, float* __restrict__ out)
{
    __shared__ __align__(16) __nv_bfloat16 As[2][128 * DROW];
    __shared__ __align__(16) __nv_bfloat16 Bs[2][128 * DROW];

    const int tid  = threadIdx.x;
    const int lane = tid & 31;
    const int warp = tid >> 5;
    const int warpM = warp >> 2;          // 0..1
    const int warpN = warp & 3;           // 0..3
    const int bm = blockIdx.y * 128;
    const int bn = blockIdx.x * 128;

    const uint32_t sA[2] = { smem_u32(As[0]), smem_u32(As[1]) };
    const uint32_t sB[2] = { smem_u32(Bs[0]), smem_u32(Bs[1]) };

    float acc[4][4][4];
#pragma unroll
    for (int i = 0; i < 4; i++)
#pragma unroll
        for (int j = 0; j < 4; j++)
#pragma unroll
            for (int r = 0; r < 4; r++) acc[i][j][r] = 0.f;

    // loader: chunk cid in [0,512): row = cid>>2, col16B = cid&3
    const int r0c = tid >> 2, c0c = tid & 3;
    const int r1c = (tid + 256) >> 2, c1c = tid & 3;   // (tid+256)&3 == tid&3

    auto issue = [&](int it, int buf) {
        const int p  = it >> 5;
        const int k0 = (it & 31) * 32;
        const __nv_bfloat16* Ap = (p < 2) ? a_hi : a_lo;
        const __nv_bfloat16* Bp = (p == 1) ? b_lo : b_hi;
        cp16(sA[buf] + (r0c * DROW + c0c * 8) * 2,
             Ap + (size_t)(bm + r0c) * H_DIM + k0 + c0c * 8);
        cp16(sA[buf] + (r1c * DROW + c1c * 8) * 2,
             Ap + (size_t)(bm + r1c) * H_DIM + k0 + c1c * 8);
        cp16(sB[buf] + (r0c * DROW + c0c * 8) * 2,
             Bp + (size_t)(bn + r0c) * H_DIM + k0 + c0c * 8);
        cp16(sB[buf] + (r1c * DROW + c1c * 8) * 2,
             Bp + (size_t)(bn + r1c) * H_DIM + k0 + c1c * 8);
    };

    issue(0, 0);
    CP_COMMIT();

    for (int it = 0; it < 96; it++) {
        const int buf = it & 1;
        if (it + 1 < 96) { issue(it + 1, buf ^ 1); CP_COMMIT(); CP_WAIT1(); }
        else             { CP_WAIT0(); }
        __syncthreads();

#pragma unroll
        for (int ks = 0; ks < 2; ks++) {
            uint32_t af[4][4];
#pragma unroll
            for (int mf = 0; mf < 4; mf++) {
                int row = warpM * 64 + mf * 16 + (lane & 15);
                int ch  = ks * 2 + (lane >> 4);
                ldsm_x4(af[mf], sA[buf] + (row * DROW + ch * 8) * 2);
            }
            uint32_t br[2][4];
#pragma unroll
            for (int g = 0; g < 2; g++) {
                int row = warpN * 32 + g * 16 + ((lane >> 4) << 3) + (lane & 7);
                int ch  = ks * 2 + ((lane >> 3) & 1);
                ldsm_x4(br[g], sB[buf] + (row * DROW + ch * 8) * 2);
            }
#pragma unroll
            for (int mf = 0; mf < 4; mf++)
#pragma unroll
                for (int g = 0; g < 2; g++) {
                    mma16816(acc[mf][g * 2],     af[mf], &br[g][0]);
                    mma16816(acc[mf][g * 2 + 1], af[mf], &br[g][2]);
                }
        }
        __syncthreads();
    }

    // epilogue
#pragma unroll
    for (int mf = 0; mf < 4; mf++) {
        int rowA = bm + warpM * 64 + mf * 16 + (lane >> 2);
        int rowB = rowA + 8;
#pragma unroll
        for (int nf = 0; nf < 4; nf++) {
            int col = bn + warpN * 32 + nf * 8 + (lane & 3) * 2;
            float b0 = (col     < V_SZ) ? bias[col]     : 0.f;
            float b1 = (col + 1 < V_SZ) ? bias[col + 1] : 0.f;
            if (col < V_SZ)     out[(size_t)rowA * V_SZ + col]     = acc[mf][nf][0] + b0;
            if (col + 1 < V_SZ) out[(size_t)rowA * V_SZ + col + 1] = acc[mf][nf][1] + b1;
            if (col < V_SZ)     out[(size_t)rowB * V_SZ + col]     = acc[mf][nf][2] + b0;
            if (col + 1 < V_SZ) out[(size_t)rowB * V_SZ + col + 1] = acc[mf][nf][3] + b1;
        }
    }
}

// ---------------- launcher --------------------------------------------------
extern "C" void kernel_launch(void* const* d_in, const int* in_sizes, int n_in,
                              void* d_out, int out_size)
{
    const int*   tokens = (const int*)  d_in[0];
    const float* h0     = (const float*)d_in[1];
    const float* c0     = (const float*)d_in[2];
    const float* emb    = (const float*)d_in[3];
    const float* Wih    = (const float*)d_in[4];
    const float* Whh    = (const float*)d_in[5];
    const float* bih    = (const float*)d_in[6];
    const float* bhh    = (const float*)d_in[7];
    const float* Whh2   = (const float*)d_in[8];
    const float* bhh2   = (const float*)d_in[9];
    const float* Whm    = (const float*)d_in[10];
    const float* bhm    = (const float*)d_in[11];
    const float* decW   = (const float*)d_in[12];
    const float* decb   = (const float*)d_in[13];
    const int*   kp     = (const int*)  d_in[14];
    float* out = (float*)d_out;

    void *p_xW, *p_hs, *p_outb, *p_c, *p_hm, *p_ah, *p_al, *p_bh, *p_bl;
    cudaGetSymbolAddress(&p_xW,   g_xW);
    cudaGetSymbolAddress(&p_hs,   g_hs);
    cudaGetSymbolAddress(&p_outb, g_outbuf);
    cudaGetSymbolAddress(&p_c,    g_c);
    cudaGetSymbolAddress(&p_hm,   g_hm);
    cudaGetSymbolAddress(&p_ah,   g_a_hi);
    cudaGetSymbolAddress(&p_al,   g_a_lo);
    cudaGetSymbolAddress(&p_bh,   g_b_hi);
    cudaGetSymbolAddress(&p_bl,   g_b_lo);
    float* xW   = (float*)p_xW;
    float* hs   = (float*)p_hs;
    float* ob   = (float*)p_outb;
    float* cbuf = (float*)p_c;
    float* hm   = (float*)p_hm;
    __nv_bfloat16* ah = (__nv_bfloat16*)p_ah;
    __nv_bfloat16* al = (__nv_bfloat16*)p_al;
    __nv_bfloat16* bh = (__nv_bfloat16*)p_bh;
    __nv_bfloat16* bl = (__nv_bfloat16*)p_bl;

    cudaFuncSetAttribute(lstm_step, cudaFuncAttributeMaxDynamicSharedMemorySize,
                         LSTM_SMEM);

    const int M = S_LEN * B_SZ;   // 2048

    // 1) xW = gather(emb, tokens) @ Wih^T + bih + bhh      (2048 x 4096)
    gemm_k<1><<<dim3(G4 / 128, M / 128), 256>>>(
        emb, Wih, xW, M, G4, E_DIM, bih, bhh, tokens, nullptr, nullptr);

    // split decW -> bf16 hi/lo (padded to V_PAD rows)
    split_b_k<<<(V_PAD * H_DIM / 4 + 255) / 256, 256>>>(decW, bh, bl);

    // 2) hm = h0 @ Whm^T + bhm                             (16 x 1024)
    gemm_k<0><<<dim3(H_DIM / 128, 1), 256>>>(
        h0, Whm, hm, B_SZ, H_DIM, H_DIM, bhm, nullptr, nullptr, nullptr, nullptr);

    // 3) c <- c0
    cudaMemcpyAsync(cbuf, c0, B_SZ * H_DIM * sizeof(float),
                    cudaMemcpyDeviceToDevice, 0);

    // 4) 128 recurrent steps
    for (int t = 0; t < S_LEN; t++) {
        const float* hp = (t == 0) ? h0 : (hs + (size_t)(t - 1) * B_SZ * H_DIM);
        lstm_step<<<128, 256, LSTM_SMEM>>>(
            hp, Whh, xW + (size_t)t * B_SZ * G4, cbuf,
            hs + (size_t)t * B_SZ * H_DIM);
    }

    // 5) outputs = (s<k) ? hs : hs @ Whh2^T + bhh2 + hm    (2048 x 1024)
    gemm_k<2><<<dim3(H_DIM / 128, M / 128), 256>>>(
        hs, Whh2, ob, M, H_DIM, H_DIM, bhh2, nullptr, nullptr, hm, kp);

    // split outputs -> bf16 hi/lo
    split_a_k<<<(M * H_DIM / 4 + 255) / 256, 256>>>(ob, ah, al, M * H_DIM / 4);

    // 6) decoded = outputs @ decW^T + decb  — mma.sync bf16-split GEMM
    dec_gemm<<<dim3(V_PAD / 128, M / 128), 256>>>(ah, al, bh, bl, decb, out);

    (void)in_sizes; (void)n_in; (void)out_size;
}

// round 6
// speedup vs baseline: 1.5541x; 1.0105x over previous
#include <cuda_runtime.h>
#include <cuda_bf16.h>
#include <cstdint>

// Problem dims (fixed by the dataset)
#define S_LEN 128
#define B_SZ  16
#define H_DIM 1024
#define E_DIM 1024
#define G4    4096
#define V_SZ  50257
#define V_PAD 50304          // 393 * 128

// ---------------- scratch (device globals; no allocation allowed) ----------
__device__ float g_xW [S_LEN * G4 * B_SZ];       // transposed: [t][j][b]
__device__ float g_hs [S_LEN * B_SZ * H_DIM];
__device__ float g_outbuf[S_LEN * B_SZ * H_DIM];
__device__ float g_hm [B_SZ * H_DIM];
__device__ unsigned int g_bar;
__device__ __align__(256) __nv_bfloat16 g_a_hi[S_LEN * B_SZ * H_DIM];
__device__ __align__(256) __nv_bfloat16 g_a_lo[S_LEN * B_SZ * H_DIM];
__device__ __align__(256) __nv_bfloat16 g_b_hi[(size_t)V_PAD * H_DIM];
__device__ __align__(256) __nv_bfloat16 g_b_lo[(size_t)V_PAD * H_DIM];

// ---------------- f32x2 helpers --------------------------------------------
__device__ __forceinline__ unsigned long long dup2(float x) {
    unsigned long long r; asm("mov.b64 %0, {%1, %1};" : "=l"(r) : "f"(x)); return r;
}
__device__ __forceinline__ unsigned long long pk2(float lo, float hi) {
    unsigned long long r; asm("mov.b64 %0, {%1, %2};" : "=l"(r) : "f"(lo), "f"(hi)); return r;
}
__device__ __forceinline__ void fma2(unsigned long long& d,
                                     unsigned long long a, unsigned long long b) {
    asm("fma.rn.f32x2 %0, %1, %2, %0;" : "+l"(d) : "l"(a), "l"(b));
}
__device__ __forceinline__ float2 up2(unsigned long long v) {
    float2 f; asm("mov.b64 {%0, %1}, %2;" : "=f"(f.x), "=f"(f.y) : "l"(v)); return f;
}
__device__ __forceinline__ float sigm(float x) { return 1.0f / (1.0f + expf(-x)); }

__device__ __forceinline__ uint32_t smem_u32(const void* p) {
    uint32_t a;
    asm("{ .reg .u64 t; cvta.to.shared.u64 t, %1; cvt.u32.u64 %0, t; }"
        : "=r"(a) : "l"(p));
    return a;
}

// ---------------- mma.sync / ldmatrix / cp.async helpers (non-'a' PTX) ------
__device__ __forceinline__ void ldsm_x4(uint32_t* r, uint32_t addr) {
    asm volatile("ldmatrix.sync.aligned.m8n8.x4.shared.b16 {%0,%1,%2,%3}, [%4];"
                 : "=r"(r[0]), "=r"(r[1]), "=r"(r[2]), "=r"(r[3]) : "r"(addr));
}
__device__ __forceinline__ void mma16816(float* c, const uint32_t* a, const uint32_t* b) {
    asm volatile(
        "mma.sync.aligned.m16n8k16.row.col.f32.bf16.bf16.f32 "
        "{%0,%1,%2,%3}, {%4,%5,%6,%7}, {%8,%9}, {%0,%1,%2,%3};"
        : "+f"(c[0]), "+f"(c[1]), "+f"(c[2]), "+f"(c[3])
        : "r"(a[0]), "r"(a[1]), "r"(a[2]), "r"(a[3]), "r"(b[0]), "r"(b[1]));
}
__device__ __forceinline__ void cp16(uint32_t dst, const void* src) {
    asm volatile("cp.async.cg.shared.global [%0], [%1], 16;" :: "r"(dst), "l"(src));
}
#define CP_COMMIT() asm volatile("cp.async.commit_group;" ::: "memory")
#define CP_WAIT1()  asm volatile("cp.async.wait_group 1;" ::: "memory")
#define CP_WAIT0()  asm volatile("cp.async.wait_group 0;" ::: "memory")

// ---------------- generic tiled fp32 GEMM (steps 1,2,5) ---------------------
// MODE 0: C = acc + bias0[n]
// MODE 1: gather-A via gidx; writes TRANSPOSED xW layout [(m/16)*G4+n]*16+(m%16)
// MODE 2: trans/mask epilogue
template <int MODE>
__global__ void __launch_bounds__(256)
gemm_k(const float* __restrict__ A, const float* __restrict__ Bm,
       float* __restrict__ C, int M, int N, int K,
       const float* __restrict__ bias0, const float* __restrict__ bias1,
       const int* __restrict__ gidx, const float* __restrict__ hmv,
       const int* __restrict__ kptr)
{
    constexpr int BM = 128, BN = 128, BK = 16;
    __shared__ float As[BK][BM + 4];
    __shared__ float Bs[BK][BN + 4];

    const int tid = threadIdx.x;
    const int bm = blockIdx.y * BM;
    const int bn = blockIdx.x * BN;
    const int tx = tid & 15;
    const int ty = tid >> 4;
    const int lr = tid >> 2;
    const int lk = (tid & 3) * 4;

    unsigned long long acc[8][4];
#pragma unroll
    for (int i = 0; i < 8; i++)
#pragma unroll
        for (int j = 0; j < 4; j++) acc[i][j] = 0ull;

    const float* arow0;
    const float* arow1;
    {
        int m0 = bm + lr, m1 = bm + lr + 64;
        if (MODE == 1) {
            arow0 = (m0 < M) ? A + (size_t)gidx[m0] * K : nullptr;
            arow1 = (m1 < M) ? A + (size_t)gidx[m1] * K : nullptr;
        } else {
            arow0 = (m0 < M) ? A + (size_t)m0 * K : nullptr;
            arow1 = (m1 < M) ? A + (size_t)m1 * K : nullptr;
        }
    }
    const int n0 = bn + lr, n1 = bn + lr + 64;
    const float* brow0 = (n0 < N) ? Bm + (size_t)n0 * K : nullptr;
    const float* brow1 = (n1 < N) ? Bm + (size_t)n1 * K : nullptr;

    const float4 fz = make_float4(0.f, 0.f, 0.f, 0.f);

    for (int k0 = 0; k0 < K; k0 += BK) {
        float4 a0 = arow0 ? *(const float4*)(arow0 + k0 + lk) : fz;
        float4 a1 = arow1 ? *(const float4*)(arow1 + k0 + lk) : fz;
        float4 b0 = brow0 ? *(const float4*)(brow0 + k0 + lk) : fz;
        float4 b1 = brow1 ? *(const float4*)(brow1 + k0 + lk) : fz;

        __syncthreads();
        As[lk + 0][lr] = a0.x;  As[lk + 1][lr] = a0.y;
        As[lk + 2][lr] = a0.z;  As[lk + 3][lr] = a0.w;
        As[lk + 0][lr + 64] = a1.x;  As[lk + 1][lr + 64] = a1.y;
        As[lk + 2][lr + 64] = a1.z;  As[lk + 3][lr + 64] = a1.w;
        Bs[lk + 0][lr] = b0.x;  Bs[lk + 1][lr] = b0.y;
        Bs[lk + 2][lr] = b0.z;  Bs[lk + 3][lr] = b0.w;
        Bs[lk + 0][lr + 64] = b1.x;  Bs[lk + 1][lr + 64] = b1.y;
        Bs[lk + 2][lr + 64] = b1.z;  Bs[lk + 3][lr + 64] = b1.w;
        __syncthreads();

#pragma unroll
        for (int kk = 0; kk < BK; kk++) {
            float4 av0 = *(const float4*)&As[kk][ty * 8];
            float4 av1 = *(const float4*)&As[kk][ty * 8 + 4];
            float4 bv0 = *(const float4*)&Bs[kk][tx * 8];
            float4 bv1 = *(const float4*)&Bs[kk][tx * 8 + 4];
            unsigned long long a2[8] = {dup2(av0.x), dup2(av0.y), dup2(av0.z), dup2(av0.w),
                                        dup2(av1.x), dup2(av1.y), dup2(av1.z), dup2(av1.w)};
            unsigned long long b2[4] = {pk2(bv0.x, bv0.y), pk2(bv0.z, bv0.w),
                                        pk2(bv1.x, bv1.y), pk2(bv1.z, bv1.w)};
#pragma unroll
            for (int i = 0; i < 8; i++)
#pragma unroll
                for (int j = 0; j < 4; j++) fma2(acc[i][j], a2[i], b2[j]);
        }
    }

    const int kval = (MODE == 2) ? *kptr : 0;

#pragma unroll
    for (int i = 0; i < 8; i++) {
        int m = bm + ty * 8 + i;
        if (m >= M) continue;
        size_t crow = (size_t)m * N;
        int srow = m >> 4;
        int b    = m & 15;
        bool cp = (MODE == 2) && (srow < kval);
#pragma unroll
        for (int j = 0; j < 4; j++) {
            float2 v = up2(acc[i][j]);
            int n = bn + tx * 8 + 2 * j;
            float vals[2] = {v.x, v.y};
#pragma unroll
            for (int u = 0; u < 2; u++) {
                int nn = n + u;
                if (nn >= N) continue;
                float r;
                if (MODE == 0)      r = vals[u] + bias0[nn];
                else if (MODE == 1) r = vals[u] + bias0[nn] + bias1[nn];
                else                r = cp ? A[(size_t)m * K + nn]
                                           : vals[u] + bias0[nn] + hmv[b * H_DIM + nn];
                if (MODE == 1)
                    C[((size_t)srow * G4 + nn) * 16 + b] = r;   // transposed xW
                else
                    C[crow + nn] = r;
            }
        }
    }
}

// ---------------- persistent LSTM scan --------------------------------------
// One launch. 128 blocks x 256 threads; block owns 8 hidden cols x 4 gates.
// Whh slice (32 rows x 1024) cached in smem once. Grid barrier via atomic.
// smem: Wsm 128KB + hT 72KB (pf aliases hT) + sg 2KB = ~202KB.
#define HT_STRIDE 18
#define PF_STRIDE 514
#define LP_W_FLOATS (32 * 1024)
#define LP_HT_FLOATS (H_DIM * HT_STRIDE)          // 18432 >= pf 16448
#define LP_SG 512
#define LP_SMEM ((LP_W_FLOATS + LP_HT_FLOATS + LP_SG) * 4)

__global__ void __launch_bounds__(256, 1)
lstm_scan(const float* __restrict__ h0,
          const float* __restrict__ c0,
          const float* __restrict__ Whh,
          const float* __restrict__ xW,       // [t][j][b]
          float* __restrict__ hs,
          unsigned int* __restrict__ bar)
{
    extern __shared__ float sh[];
    float* Wsm = sh;                              // [32][1024]
    float* hT  = sh + LP_W_FLOATS;                // [1024][18]
    float* pf  = hT;                              // aliases hT: [32][514]
    float* sg  = sh + LP_W_FLOATS + LP_HT_FLOATS; // [32][16]

    const int tid = threadIdx.x;
    const int hb  = blockIdx.x * 8;
    const int kt  = tid & 31;
    const int jt  = tid >> 5;

    // ---- preload W slice into smem (once) ----
#pragma unroll 4
    for (int ll = 0; ll < 32; ll++) {
        int j = (ll >> 3) * H_DIM + hb + (ll & 7);
        ((float4*)(Wsm + ll * H_DIM))[tid] =
            ((const float4*)(Whh + (size_t)j * H_DIM))[tid];
    }

    // ---- cell state in registers (threads 0..127) ----
    float cloc = 0.f;
    const int a_hil = tid >> 4;       // 0..7  (valid for tid<128)
    const int a_b   = tid & 15;
    if (tid < 128) cloc = c0[a_b * H_DIM + hb + a_hil];

    const float* wrow[4];
#pragma unroll
    for (int l = 0; l < 4; l++) wrow[l] = Wsm + (jt * 4 + l) * H_DIM + kt;

    const float* hsrc = h0;

    for (int t = 0; t < S_LEN; t++) {
        // ---- stage h transposed (L2 reads, bypass L1) ----
        {
            const int b   = tid & 15;
            const int e4b = tid >> 4;
            const float4* hp = (const float4*)(hsrc + b * H_DIM);
#pragma unroll
            for (int i = 0; i < 16; i++) {
                int e4 = e4b + 16 * i;
                float4 v = __ldcg(hp + e4);
                int e0 = e4 * 4;
                hT[(e0 + 0) * HT_STRIDE + b] = v.x;
                hT[(e0 + 1) * HT_STRIDE + b] = v.y;
                hT[(e0 + 2) * HT_STRIDE + b] = v.z;
                hT[(e0 + 3) * HT_STRIDE + b] = v.w;
            }
        }
        __syncthreads();

        // ---- partial GEMM: lane kt covers k = kt + 32*i ----
        unsigned long long acc[4][8];
#pragma unroll
        for (int l = 0; l < 4; l++)
#pragma unroll
            for (int bp = 0; bp < 8; bp++) acc[l][bp] = 0ull;

#pragma unroll 4
        for (int i = 0; i < 32; i++) {
            const int k = kt + 32 * i;
            const unsigned long long* hrow =
                (const unsigned long long*)(hT + k * HT_STRIDE);
            unsigned long long hv[8];
#pragma unroll
            for (int bp = 0; bp < 8; bp++) hv[bp] = hrow[bp];
            float w0 = wrow[0][32 * i], w1 = wrow[1][32 * i];
            float w2 = wrow[2][32 * i], w3 = wrow[3][32 * i];
            unsigned long long wd0 = dup2(w0), wd1 = dup2(w1);
            unsigned long long wd2 = dup2(w2), wd3 = dup2(w3);
#pragma unroll
            for (int bp = 0; bp < 8; bp++) {
                fma2(acc[0][bp], wd0, hv[bp]);
                fma2(acc[1][bp], wd1, hv[bp]);
                fma2(acc[2][bp], wd2, hv[bp]);
                fma2(acc[3][bp], wd3, hv[bp]);
            }
        }
        __syncthreads();   // hT reads done before pf (alias) writes

        {
            unsigned long long* pr =
                (unsigned long long*)(pf + kt * PF_STRIDE + (jt * 4) * 16);
#pragma unroll
            for (int l = 0; l < 4; l++)
#pragma unroll
                for (int bp = 0; bp < 8; bp++) pr[l * 8 + bp] = acc[l][bp];
        }
        __syncthreads();

        // ---- reduce over kt, add xW bias term ----
        {
            const int l = tid >> 3;
            const int b = (tid & 7) * 2;
            float s0 = 0.f, s1 = 0.f;
            const float* p = pf + l * 16 + b;
#pragma unroll 8
            for (int ktt = 0; ktt < 32; ktt++) {
                float2 v = *(const float2*)(p + ktt * PF_STRIDE);
                s0 += v.x; s1 += v.y;
            }
            const int j = (l >> 3) * H_DIM + hb + (l & 7);
            const float2 xv = *(const float2*)(xW + ((size_t)t * G4 + j) * 16 + b);
            sg[l * 16 + b]     = s0 + xv.x;
            sg[l * 16 + b + 1] = s1 + xv.y;
        }
        __syncthreads();

        // ---- activation + state update + publish h ----
        if (tid < 128) {
            float gi = sg[(0  + a_hil) * 16 + a_b];
            float gf = sg[(8  + a_hil) * 16 + a_b];
            float gg = sg[(16 + a_hil) * 16 + a_b];
            float go = sg[(24 + a_hil) * 16 + a_b];
            float cn = sigm(gf) * cloc + sigm(gi) * tanhf(gg);
            cloc = cn;
            hs[(size_t)t * B_SZ * H_DIM + a_b * H_DIM + hb + a_hil] =
                sigm(go) * tanhf(cn);
        }
        __threadfence();
        __syncthreads();

        // ---- grid barrier ----
        if (tid == 0) {
            atomicAdd(bar, 1u);
            const unsigned int target = 128u * (unsigned)(t + 1);
            while (*((volatile unsigned int*)bar) < target) { }
        }
        __syncthreads();

        hsrc = hs + (size_t)t * B_SZ * H_DIM;
    }
}

// ---------------- bf16 hi/lo split kernels ----------------------------------
__global__ void __launch_bounds__(256)
split_a_k(const float* __restrict__ src, __nv_bfloat16* __restrict__ hi,
          __nv_bfloat16* __restrict__ lo, int n4)
{
    int i = blockIdx.x * blockDim.x + threadIdx.x;
    if (i >= n4) return;
    float4 v = ((const float4*)src)[i];
    float xs[4] = {v.x, v.y, v.z, v.w};
    __nv_bfloat16 h[4], l[4];
#pragma unroll
    for (int j = 0; j < 4; j++) {
        h[j] = __float2bfloat16_rn(xs[j]);
        l[j] = __float2bfloat16_rn(xs[j] - __bfloat162float(h[j]));
    }
    ((__nv_bfloat162*)hi)[2 * i]     = __halves2bfloat162(h[0], h[1]);
    ((__nv_bfloat162*)hi)[2 * i + 1] = __halves2bfloat162(h[2], h[3]);
    ((__nv_bfloat162*)lo)[2 * i]     = __halves2bfloat162(l[0], l[1]);
    ((__nv_bfloat162*)lo)[2 * i + 1] = __halves2bfloat162(l[2], l[3]);
}

__global__ void __launch_bounds__(256)
split_b_k(const float* __restrict__ src, __nv_bfloat16* __restrict__ hi,
          __nv_bfloat16* __restrict__ lo)
{
    int i = blockIdx.x * blockDim.x + threadIdx.x;
    if (i >= V_PAD * (H_DIM / 4)) return;
    int row = i >> 8;
    float4 v = make_float4(0.f, 0.f, 0.f, 0.f);
    if (row < V_SZ) v = ((const float4*)src)[i];
    float xs[4] = {v.x, v.y, v.z, v.w};
    __nv_bfloat16 h[4], l[4];
#pragma unroll
    for (int j = 0; j < 4; j++) {
        h[j] = __float2bfloat16_rn(xs[j]);
        l[j] = __float2bfloat16_rn(xs[j] - __bfloat162float(h[j]));
    }
    ((__nv_bfloat162*)hi)[2 * i]     = __halves2bfloat162(h[0], h[1]);
    ((__nv_bfloat162*)hi)[2 * i + 1] = __halves2bfloat162(h[2], h[3]);
    ((__nv_bfloat162*)lo)[2 * i]     = __halves2bfloat162(l[0], l[1]);
    ((__nv_bfloat162*)lo)[2 * i + 1] = __halves2bfloat162(l[2], l[3]);
}

// ---------------- mma.sync decoder GEMM (unchanged from R5) -----------------
#define DROW 40

__global__ void __launch_bounds__(256, 1)
dec_gemm(const __nv_bfloat16* __restrict__ a_hi, const __nv_bfloat16* __restrict__ a_lo,
         const __nv_bfloat16* __restrict__ b_hi, const __nv_bfloat16* __restrict__ b_lo,
         const float* __restrict__ bias, float* __restrict__ out)
{
    __shared__ __align__(16) __nv_bfloat16 As[2][128 * DROW];
    __shared__ __align__(16) __nv_bfloat16 Bs[2][128 * DROW];

    const int tid  = threadIdx.x;
    const int lane = tid & 31;
    const int warp = tid >> 5;
    const int warpM = warp >> 2;
    const int warpN = warp & 3;
    const int bm = blockIdx.y * 128;
    const int bn = blockIdx.x * 128;

    const uint32_t sA[2] = { smem_u32(As[0]), smem_u32(As[1]) };
    const uint32_t sB[2] = { smem_u32(Bs[0]), smem_u32(Bs[1]) };

    float acc[4][4][4];
#pragma unroll
    for (int i = 0; i < 4; i++)
#pragma unroll
        for (int j = 0; j < 4; j++)
#pragma unroll
            for (int r = 0; r < 4; r++) acc[i][j][r] = 0.f;

    const int r0c = tid >> 2, c0c = tid & 3;
    const int r1c = (tid + 256) >> 2, c1c = tid & 3;

    auto issue = [&](int it, int buf) {
        const int p  = it >> 5;
        const int k0 = (it & 31) * 32;
        const __nv_bfloat16* Ap = (p < 2) ? a_hi : a_lo;
        const __nv_bfloat16* Bp = (p == 1) ? b_lo : b_hi;
        cp16(sA[buf] + (r0c * DROW + c0c * 8) * 2,
             Ap + (size_t)(bm + r0c) * H_DIM + k0 + c0c * 8);
        cp16(sA[buf] + (r1c * DROW + c1c * 8) * 2,
             Ap + (size_t)(bm + r1c) * H_DIM + k0 + c1c * 8);
        cp16(sB[buf] + (r0c * DROW + c0c * 8) * 2,
             Bp + (size_t)(bn + r0c) * H_DIM + k0 + c0c * 8);
        cp16(sB[buf] + (r1c * DROW + c1c * 8) * 2,
             Bp + (size_t)(bn + r1c) * H_DIM + k0 + c1c * 8);
    };

    issue(0, 0);
    CP_COMMIT();

    for (int it = 0; it < 96; it++) {
        const int buf = it & 1;
        if (it + 1 < 96) { issue(it + 1, buf ^ 1); CP_COMMIT(); CP_WAIT1(); }
        else             { CP_WAIT0(); }
        __syncthreads();

#pragma unroll
        for (int ks = 0; ks < 2; ks++) {
            uint32_t af[4][4];
#pragma unroll
            for (int mf = 0; mf < 4; mf++) {
                int row = warpM * 64 + mf * 16 + (lane & 15);
                int ch  = ks * 2 + (lane >> 4);
                ldsm_x4(af[mf], sA[buf] + (row * DROW + ch * 8) * 2);
            }
            uint32_t br[2][4];
#pragma unroll
            for (int g = 0; g < 2; g++) {
                int row = warpN * 32 + g * 16 + ((lane >> 4) << 3) + (lane & 7);
                int ch  = ks * 2 + ((lane >> 3) & 1);
                ldsm_x4(br[g], sB[buf] + (row * DROW + ch * 8) * 2);
            }
#pragma unroll
            for (int mf = 0; mf < 4; mf++)
#pragma unroll
                for (int g = 0; g < 2; g++) {
                    mma16816(acc[mf][g * 2],     af[mf], &br[g][0]);
                    mma16816(acc[mf][g * 2 + 1], af[mf], &br[g][2]);
                }
        }
        __syncthreads();
    }

#pragma unroll
    for (int mf = 0; mf < 4; mf++) {
        int rowA = bm + warpM * 64 + mf * 16 + (lane >> 2);
        int rowB = rowA + 8;
#pragma unroll
        for (int nf = 0; nf < 4; nf++) {
            int col = bn + warpN * 32 + nf * 8 + (lane & 3) * 2;
            float b0 = (col     < V_SZ) ? bias[col]     : 0.f;
            float b1 = (col + 1 < V_SZ) ? bias[col + 1] : 0.f;
            if (col < V_SZ)     out[(size_t)rowA * V_SZ + col]     = acc[mf][nf][0] + b0;
            if (col + 1 < V_SZ) out[(size_t)rowA * V_SZ + col + 1] = acc[mf][nf][1] + b1;
            if (col < V_SZ)     out[(size_t)rowB * V_SZ + col]     = acc[mf][nf][2] + b0;
            if (col + 1 < V_SZ) out[(size_t)rowB * V_SZ + col + 1] = acc[mf][nf][3] + b1;
        }
    }
}

// ---------------- launcher --------------------------------------------------
extern "C" void kernel_launch(void* const* d_in, const int* in_sizes, int n_in,
                              void* d_out, int out_size)
{
    const int*   tokens = (const int*)  d_in[0];
    const float* h0     = (const float*)d_in[1];
    const float* c0     = (const float*)d_in[2];
    const float* emb    = (const float*)d_in[3];
    const float* Wih    = (const float*)d_in[4];
    const float* Whh    = (const float*)d_in[5];
    const float* bih    = (const float*)d_in[6];
    const float* bhh    = (const float*)d_in[7];
    const float* Whh2   = (const float*)d_in[8];
    const float* bhh2   = (const float*)d_in[9];
    const float* Whm    = (const float*)d_in[10];
    const float* bhm    = (const float*)d_in[11];
    const float* decW   = (const float*)d_in[12];
    const float* decb   = (const float*)d_in[13];
    const int*   kp     = (const int*)  d_in[14];
    float* out = (float*)d_out;

    void *p_xW, *p_hs, *p_outb, *p_hm, *p_bar, *p_ah, *p_al, *p_bh, *p_bl;
    cudaGetSymbolAddress(&p_xW,   g_xW);
    cudaGetSymbolAddress(&p_hs,   g_hs);
    cudaGetSymbolAddress(&p_outb, g_outbuf);
    cudaGetSymbolAddress(&p_hm,   g_hm);
    cudaGetSymbolAddress(&p_bar,  g_bar);
    cudaGetSymbolAddress(&p_ah,   g_a_hi);
    cudaGetSymbolAddress(&p_al,   g_a_lo);
    cudaGetSymbolAddress(&p_bh,   g_b_hi);
    cudaGetSymbolAddress(&p_bl,   g_b_lo);
    float* xW   = (float*)p_xW;
    float* hs   = (float*)p_hs;
    float* ob   = (float*)p_outb;
    float* hm   = (float*)p_hm;
    unsigned int* bar = (unsigned int*)p_bar;
    __nv_bfloat16* ah = (__nv_bfloat16*)p_ah;
    __nv_bfloat16* al = (__nv_bfloat16*)p_al;
    __nv_bfloat16* bh = (__nv_bfloat16*)p_bh;
    __nv_bfloat16* bl = (__nv_bfloat16*)p_bl;

    cudaFuncSetAttribute(lstm_scan, cudaFuncAttributeMaxDynamicSharedMemorySize,
                         LP_SMEM);

    const int M = S_LEN * B_SZ;   // 2048

    // 1) xW = gather(emb, tokens) @ Wih^T + bih + bhh  -> transposed [t][j][b]
    gemm_k<1><<<dim3(G4 / 128, M / 128), 256>>>(
        emb, Wih, xW, M, G4, E_DIM, bih, bhh, tokens, nullptr, nullptr);

    // split decW -> bf16 hi/lo (padded to V_PAD rows)
    split_b_k<<<(V_PAD * H_DIM / 4 + 255) / 256, 256>>>(decW, bh, bl);

    // 2) hm = h0 @ Whm^T + bhm
    gemm_k<0><<<dim3(H_DIM / 128, 1), 256>>>(
        h0, Whm, hm, B_SZ, H_DIM, H_DIM, bhm, nullptr, nullptr, nullptr, nullptr);

    // 3) reset grid barrier
    cudaMemsetAsync(bar, 0, sizeof(unsigned int), 0);

    // 4) persistent LSTM scan (one launch, 128 internal steps)
    lstm_scan<<<128, 256, LP_SMEM>>>(h0, c0, Whh, xW, hs, bar);

    // 5) outputs = (s<k) ? hs : hs @ Whh2^T + bhh2 + hm
    gemm_k<2><<<dim3(H_DIM / 128, M / 128), 256>>>(
        hs, Whh2, ob, M, H_DIM, H_DIM, bhh2, nullptr, nullptr, hm, kp);

    // split outputs -> bf16 hi/lo
    split_a_k<<<(M * H_DIM / 4 + 255) / 256, 256>>>(ob, ah, al, M * H_DIM / 4);

    // 6) decoded = outputs @ decW^T + decb  — mma.sync bf16-split GEMM
    dec_gemm<<<dim3(V_PAD / 128, M / 128), 256>>>(ah, al, bh, bl, decb, out);

    (void)in_sizes; (void)n_in; (void)out_size;
}